// round 7
// baseline (speedup 1.0000x reference)
#include <cuda_runtime.h>
#include <cuda_bf16.h>
#include <math.h>
#include <stdint.h>

#define PI_D 3.14159265358979323846

__device__ __forceinline__ uint32_t smem_u32(const void* p) {
    uint32_t a;
    asm("{ .reg .u64 t; cvta.to.shared.u64 t, %1; cvt.u32.u64 %0, t; }" : "=r"(a) : "l"(p));
    return a;
}
static __device__ __forceinline__ uint32_t swz128(uint32_t off) { return off ^ ((off >> 3) & 0x70); }

__device__ __forceinline__ void cp_async16(uint32_t saddr, const void* gaddr, int sz) {
    asm volatile("cp.async.cg.shared.global [%0], [%1], 16, %2;"
                 :: "r"(saddr), "l"(gaddr), "r"(sz) : "memory");
}
__device__ __forceinline__ void ldmx4(uint32_t* r, uint32_t addr) {
    asm volatile("ldmatrix.sync.aligned.m8n8.x4.shared.b16 {%0,%1,%2,%3}, [%4];"
        : "=r"(r[0]), "=r"(r[1]), "=r"(r[2]), "=r"(r[3]) : "r"(addr));
}
__device__ __forceinline__ void mma16816(float* c, const uint32_t* a, uint32_t b0, uint32_t b1) {
    asm volatile("mma.sync.aligned.m16n8k16.row.col.f32.bf16.bf16.f32 "
        "{%0,%1,%2,%3}, {%4,%5,%6,%7}, {%8,%9}, {%0,%1,%2,%3};"
        : "+f"(c[0]), "+f"(c[1]), "+f"(c[2]), "+f"(c[3])
        : "r"(a[0]), "r"(a[1]), "r"(a[2]), "r"(a[3]), "r"(b0), "r"(b1));
}

// ---------------- device scratch ----------------
__device__ float  g_s2[256], g_b2[256];
__device__ float  g_conv[8*256*4096];
__device__ float2 g_f[8*256*4096];
__device__ float2 g_t[8*256*4096];
__device__ float  g_out2[8*512*4096];
__device__ float2 g_attnp[4*64*1024];
__device__ float2 g_M[64*1024];          // M = D32^T * softmax(attn), per (b,hd)
__device__ float  g_invn[2048];
__device__ float2 g_D64f[4096];
__device__ float2 g_D64i[4096];
__device__ float2 g_tw[4096];
__device__ float2 g_D32i[1024];
__device__ __nv_bfloat16 g_xhi[8*4096*512];
__device__ __nv_bfloat16 g_xlo[8*4096*512];
__device__ __nv_bfloat16 g_whi[9*256*512];
__device__ __nv_bfloat16 g_wlo[9*256*512];
__device__ __nv_bfloat16 g_o2hi[8*4096*512];
__device__ __nv_bfloat16 g_o2lo[8*4096*512];
__device__ __nv_bfloat16 g_pwhi[512*512];
__device__ __nv_bfloat16 g_pwlo[512*512];

// ---------------- prep ----------------
__global__ void k_split_x(const float* __restrict__ x) {
    size_t i = (size_t)blockIdx.x * 256 + threadIdx.x;
    if (i >= (size_t)8*4096*512) return;
    float v = x[i];
    __nv_bfloat16 h = __float2bfloat16(v);
    g_xhi[i] = h;
    g_xlo[i] = __float2bfloat16(v - __bfloat162float(h));
}

__global__ void k_split_w(const float* __restrict__ w) {
    int i = blockIdx.x * 256 + threadIdx.x;
    if (i >= 9*256*512) return;
    int c = i & 511, o = (i >> 9) & 255, tap = i >> 17;
    float v = w[(o*512 + c)*9 + tap];
    __nv_bfloat16 h = __float2bfloat16(v);
    g_whi[i] = h;
    g_wlo[i] = __float2bfloat16(v - __bfloat162float(h));
}

__global__ void k_split_pw(const float* __restrict__ pw) {
    int i = blockIdx.x * 256 + threadIdx.x;
    if (i >= 512*512) return;
    float v = pw[i];
    __nv_bfloat16 h = __float2bfloat16(v);
    g_pwhi[i] = h;
    g_pwlo[i] = __float2bfloat16(v - __bfloat162float(h));
}

__global__ void k_prep_misc(const float* __restrict__ conv2_b, const float* __restrict__ g,
                            const float* __restrict__ bb, const float* __restrict__ m,
                            const float* __restrict__ v) {
    int i = blockIdx.x*blockDim.x + threadIdx.x;
    if (i < 4096) {
        int j = i >> 6, k = i & 63;
        double s, c;
        sincos(2.0*PI_D*(double)(j*k)/64.0, &s, &c);
        g_D64f[i] = make_float2((float)c, (float)(-s));
        g_D64i[i] = make_float2((float)c, (float)s);
        sincos(2.0*PI_D*(double)(j*k)/4096.0, &s, &c);
        g_tw[i] = make_float2((float)c, (float)s);
    }
    if (i < 1024) {
        int j = i >> 5, k = i & 31;
        double s, c;
        sincos(2.0*PI_D*(double)(j*k)/32.0, &s, &c);
        g_D32i[i] = make_float2((float)(c/32.0), (float)(s/32.0));
    }
    if (i < 256) {
        float sc = g[i] * rsqrtf(v[i] + 1e-5f);
        g_s2[i] = sc;
        g_b2[i] = (conv2_b[i] - m[i]) * sc + bb[i];
    }
    if (i < 4*64*1024) g_attnp[i] = make_float2(0.f, 0.f);
}

// ---------------- conv via HMMA implicit GEMM ----------------
#define CH_BYTES 49152
#define CONV_STAGES 3
#define CONV_SMEM (CONV_STAGES*CH_BYTES)

__global__ void __launch_bounds__(256, 1) k_conv_hmma() {
    extern __shared__ char smem[];
    uint32_t sb = smem_u32(smem);
    int tid = threadIdx.x, wid = tid >> 5, lane = tid & 31;
    int b = blockIdx.x >> 5;
    int m0 = (blockIdx.x & 31) << 7;
    int wm = wid & 1, wn = wid >> 1;

    float c[4][8][4];
    #pragma unroll
    for (int i = 0; i < 4; i++)
        #pragma unroll
        for (int j = 0; j < 8; j++)
            #pragma unroll
            for (int r = 0; r < 4; r++) c[i][j][r] = 0.f;

    auto issue = [&](int chunk) {
        int pass = chunk / 72, rem = chunk % 72, tap = rem >> 3, c0 = (rem & 7) << 6;
        const __nv_bfloat16* xs = ((pass == 2) ? g_xlo : g_xhi) + (size_t)b*4096*512 + c0;
        const __nv_bfloat16* ws = ((pass == 1) ? g_wlo : g_whi) + (size_t)tap*256*512 + c0;
        int oy = (tap/3)*3 - 3, ox = (tap%3)*3 - 3;
        uint32_t bo = (uint32_t)(chunk % CONV_STAGES) * CH_BYTES;
        #pragma unroll
        for (int i = 0; i < 4; i++) {
            int idx = tid + i*256;
            int r = idx >> 3, q = idx & 7;
            int n = m0 + r;
            int ysr = (n >> 6) + oy, xsr = (n & 63) + ox;
            bool ok = ((unsigned)ysr < 64u) && ((unsigned)xsr < 64u);
            const __nv_bfloat16* gp = ok ? (xs + (size_t)(ysr*64 + xsr)*512 + q*8) : xs;
            cp_async16(sb + bo + swz128((uint32_t)(r*128 + q*16)), gp, ok ? 16 : 0);
        }
        #pragma unroll
        for (int i = 0; i < 8; i++) {
            int idx = tid + i*256;
            int o = idx >> 3, q = idx & 7;
            cp_async16(sb + bo + 16384u + swz128((uint32_t)(o*128 + q*16)),
                       ws + (size_t)o*512 + q*8, 16);
        }
        asm volatile("cp.async.commit_group;" ::: "memory");
    };

    issue(0); issue(1);
    int sub = lane >> 3, lr = lane & 7;
    #pragma unroll 1
    for (int ch = 0; ch < 216; ch++) {
        if (ch + 2 < 216) {
            issue(ch + 2);
            asm volatile("cp.async.wait_group 2;" ::: "memory");
        } else {
            asm volatile("cp.async.wait_group 0;" ::: "memory");
        }
        __syncthreads();
        uint32_t aBase = sb + (uint32_t)(ch % CONV_STAGES) * CH_BYTES;
        uint32_t bBase = aBase + 16384u;
        #pragma unroll
        for (int k16 = 0; k16 < 4; k16++) {
            uint32_t kb = (uint32_t)(k16*32);
            uint32_t a[4][4];
            #pragma unroll
            for (int mf = 0; mf < 4; mf++) {
                uint32_t row = (uint32_t)(wm*64 + mf*16 + ((sub & 1) << 3) + lr);
                uint32_t col = kb + ((uint32_t)(sub >> 1) << 4);
                ldmx4(a[mf], aBase + swz128(row*128 + col));
            }
            #pragma unroll
            for (int nfp = 0; nfp < 4; nfp++) {
                uint32_t brow = (uint32_t)(wn*64 + nfp*16 + ((sub & 2) << 2) + lr);
                uint32_t bcol = kb + ((uint32_t)(sub & 1) << 4);
                uint32_t bf[4];
                ldmx4(bf, bBase + swz128(brow*128 + bcol));
                #pragma unroll
                for (int mf = 0; mf < 4; mf++) {
                    mma16816(c[mf][nfp*2],     a[mf], bf[0], bf[1]);
                    mma16816(c[mf][nfp*2 + 1], a[mf], bf[2], bf[3]);
                }
            }
        }
        __syncthreads();
    }

    #pragma unroll
    for (int nf = 0; nf < 8; nf++) {
        int o = wn*64 + nf*8 + (lane & 3)*2;
        float s0 = g_s2[o],   t0 = g_b2[o];
        float s1 = g_s2[o+1], t1 = g_b2[o+1];
        float* d0 = g_conv + ((size_t)b*256 + o)*4096;
        float* d1 = d0 + 4096;
        #pragma unroll
        for (int mf = 0; mf < 4; mf++) {
            int n = m0 + wm*64 + mf*16 + (lane >> 2);
            d0[n]   = fmaxf(fmaf(c[mf][nf][0], s0, t0), 0.f);
            d1[n]   = fmaxf(fmaf(c[mf][nf][1], s1, t1), 0.f);
            d0[n+8] = fmaxf(fmaf(c[mf][nf][2], s0, t0), 0.f);
            d1[n+8] = fmaxf(fmaf(c[mf][nf][3], s1, t1), 0.f);
        }
    }
}

// ---------------- fft2 64x64 forward (real -> complex) ----------------
__global__ void k_fft2_fwd() {
    __shared__ float2 S[4096];
    int img = blockIdx.x;
    int t = threadIdx.x;
    const float* src = g_conv + (size_t)img*4096;
    for (int i=t;i<4096;i+=256) S[i] = make_float2(src[i], 0.f);
    __syncthreads();
    int k = t & 63, rg = t >> 6;
    float2 acc[16];
    #pragma unroll
    for (int i=0;i<16;i++) acc[i]=make_float2(0.f,0.f);
    for (int n=0;n<64;n++) {
        float2 d = g_D64f[n*64+k];
        #pragma unroll
        for (int i=0;i<16;i++) {
            float2 a = S[(rg*16+i)*64 + n];
            acc[i].x = fmaf(a.x, d.x, fmaf(-a.y, d.y, acc[i].x));
            acc[i].y = fmaf(a.x, d.y, fmaf( a.y, d.x, acc[i].y));
        }
    }
    __syncthreads();
    #pragma unroll
    for (int i=0;i<16;i++) S[(rg*16+i)*64 + k] = acc[i];
    __syncthreads();
    #pragma unroll
    for (int i=0;i<16;i++) acc[i]=make_float2(0.f,0.f);
    for (int r=0;r<64;r++) {
        float2 bv = S[r*64 + k];
        #pragma unroll
        for (int i=0;i<16;i++) {
            float2 d = g_D64f[r*64 + rg*16 + i];
            acc[i].x = fmaf(bv.x, d.x, fmaf(-bv.y, d.y, acc[i].x));
            acc[i].y = fmaf(bv.x, d.y, fmaf( bv.y, d.x, acc[i].y));
        }
    }
    float2* dst = g_f + (size_t)img*4096;
    #pragma unroll
    for (int i=0;i<16;i++) dst[(rg*16+i)*64 + k] = acc[i];
}

// ---------------- inverse row norms ----------------
__global__ void k_invnorm() {
    int row = blockIdx.x;
    const float2* p = g_f + (size_t)row*4096;
    float s = 0.f;
    for (int i=threadIdx.x;i<4096;i+=256) { float2 v = p[i]; s = fmaf(v.x,v.x,fmaf(v.y,v.y,s)); }
    __shared__ float red[256];
    red[threadIdx.x]=s; __syncthreads();
    for (int st=128;st>0;st>>=1){ if(threadIdx.x<st) red[threadIdx.x]+=red[threadIdx.x+st]; __syncthreads(); }
    if (threadIdx.x==0) g_invn[row] = 1.f / fmaxf(sqrtf(red[0]), 1e-12f);
}

// ---------------- attention logit partials ----------------
__global__ void k_attn() {
    __shared__ float2 F[32*65];
    int bh = blockIdx.x, p = blockIdx.y;
    int b = bh >> 3, hd = bh & 7;
    int t = threadIdx.x;
    int d = t & 31, cg = t >> 5;
    float2 acc[4];
    #pragma unroll
    for (int i=0;i<4;i++) acc[i]=make_float2(0.f,0.f);
    const float2* base = g_f + (((size_t)b*256 + hd*32)*4096);
    for (int n0 = p*1024; n0 < p*1024+1024; n0 += 64) {
        __syncthreads();
        for (int e=t; e<2048; e+=256) {
            int cc = e >> 6, j = e & 63;
            F[cc*65+j] = base[(size_t)cc*4096 + n0 + j];
        }
        __syncthreads();
        for (int j=0;j<64;j++) {
            float2 vd = F[d*65+j];
            #pragma unroll
            for (int i=0;i<4;i++) {
                float2 vc = F[(cg*4+i)*65 + j];
                acc[i].x = fmaf(vc.x,vd.x, fmaf(-vc.y,vd.y, acc[i].x));
                acc[i].y = fmaf(vc.x,vd.y, fmaf( vc.y,vd.x, acc[i].y));
            }
        }
    }
    float2* dst = g_attnp + ((size_t)p*64 + bh)*1024;
    #pragma unroll
    for (int i=0;i<4;i++) dst[(cg*4+i)*32 + d] = acc[i];
}

// ---------------- softmax + M = D32^T * attn (fused), one block per (b,hd) ----------------
__global__ void k_softmax_mkM(const float* __restrict__ temperature) {
    __shared__ float2 A[1024];
    int bh = blockIdx.x;
    int b = bh >> 3, hd = bh & 7;
    int t = threadIdx.x;
    int w = t >> 5, lane = t & 31;
    float temp = temperature[hd];
    #pragma unroll
    for (int rr = 0; rr < 4; rr++) {
        int c = w*4 + rr;
        size_t idx = (size_t)bh*1024 + c*32 + lane;
        float2 v = make_float2(0.f,0.f);
        #pragma unroll
        for (int p=0;p<4;p++){ float2 q = g_attnp[(size_t)p*65536 + idx]; v.x+=q.x; v.y+=q.y; }
        float scale = g_invn[b*256 + hd*32 + c] * g_invn[b*256 + hd*32 + lane] * temp;
        float re = v.x*scale, im = v.y*scale;
        float mre = re, mim = im;
        for (int s=16;s>0;s>>=1){ mre = fmaxf(mre, __shfl_xor_sync(0xffffffffu, mre, s));
                                  mim = fmaxf(mim, __shfl_xor_sync(0xffffffffu, mim, s)); }
        float ere = expf(re-mre), eim = expf(im-mim);
        float sre=ere, sim=eim;
        for (int s=16;s>0;s>>=1){ sre += __shfl_xor_sync(0xffffffffu,sre,s);
                                  sim += __shfl_xor_sync(0xffffffffu,sim,s); }
        A[c*32 + lane] = make_float2(ere/sre, eim/sim);
    }
    __syncthreads();
    // M[k][d] = sum_c D32i[c][k] * A[c][d]
    int d = t & 31, kg = t >> 5;
    #pragma unroll
    for (int kk = 0; kk < 4; kk++) {
        int k = kg*4 + kk;
        float2 acc = make_float2(0.f, 0.f);
        for (int c = 0; c < 32; c++) {
            float2 Dv = g_D32i[c*32 + k];
            float2 av = A[c*32 + d];
            acc.x = fmaf(Dv.x, av.x, fmaf(-Dv.y, av.y, acc.x));
            acc.y = fmaf(Dv.x, av.y, fmaf( Dv.y, av.x, acc.y));
        }
        g_M[(size_t)bh*1024 + k*32 + d] = acc;
    }
}

// ---------------- apply (M = ifft32-folded attention) ----------------
__global__ void k_apply() {
    __shared__ float2 As[1024];
    int bh = blockIdx.x, nc = blockIdx.y;
    int b = bh>>3, hd = bh&7;
    int t = threadIdx.x;
    for (int e=t;e<1024;e+=256) As[e] = g_M[(size_t)bh*1024 + e];
    __syncthreads();
    int n = nc*256 + t;
    const float2* fb = g_f + ((size_t)b*256 + hd*32)*4096 + n;
    float2 acc[32];
    #pragma unroll
    for (int c=0;c<32;c++) acc[c]=make_float2(0.f,0.f);
    for (int d=0;d<32;d++) {
        float2 v = fb[(size_t)d*4096];
        #pragma unroll
        for (int c=0;c<32;c++) {
            float2 a = As[c*32+d];
            acc[c].x = fmaf(a.x,v.x, fmaf(-a.y,v.y, acc[c].x));
            acc[c].y = fmaf(a.x,v.y, fmaf( a.y,v.x, acc[c].y));
        }
    }
    float2* ob = g_t + ((size_t)b*256 + hd*32)*4096 + n;
    #pragma unroll
    for (int c=0;c<32;c++) ob[(size_t)c*4096] = acc[c];
}

// ---------------- ifft-4096 per row ----------------
__global__ void k_ifft4096() {
    __shared__ float2 S[4224];
    int row = blockIdx.x;
    int t = threadIdx.x;
    const float2* src = g_t + (size_t)row*4096;
    for (int i=t;i<4096;i+=256) S[i]=src[i];
    __syncthreads();
    int k = t&63, rg = t>>6;
    float2 acc[16];
    #pragma unroll
    for(int i=0;i<16;i++)acc[i]=make_float2(0.f,0.f);
    for (int n1=0;n1<64;n1++){
        float2 a = S[n1*64 + k];
        #pragma unroll
        for (int i=0;i<16;i++){
            float2 d = g_D64i[n1*64 + rg*16+i];
            acc[i].x = fmaf(a.x,d.x,fmaf(-a.y,d.y,acc[i].x));
            acc[i].y = fmaf(a.x,d.y,fmaf( a.y,d.x,acc[i].y));
        }
    }
    __syncthreads();
    #pragma unroll
    for (int i=0;i<16;i++){
        int k1 = rg*16+i;
        float2 tw = g_tw[k*64 + k1];
        float2 v; v.x = acc[i].x*tw.x - acc[i].y*tw.y; v.y = acc[i].x*tw.y + acc[i].y*tw.x;
        S[k1*64 + k] = v;
    }
    __syncthreads();
    #pragma unroll
    for(int i=0;i<16;i++)acc[i]=make_float2(0.f,0.f);
    for (int n2=0;n2<64;n2++){
        float2 d = g_D64i[n2*64 + k];
        #pragma unroll
        for (int i=0;i<16;i++){
            float2 bv = S[(rg*16+i)*64 + n2];
            acc[i].x = fmaf(bv.x,d.x,fmaf(-bv.y,d.y,acc[i].x));
            acc[i].y = fmaf(bv.x,d.y,fmaf( bv.y,d.x,acc[i].y));
        }
    }
    __syncthreads();
    #pragma unroll
    for (int i=0;i<16;i++) S[k*66 + rg*16+i] = acc[i];
    __syncthreads();
    int b = row >> 8, ch = row & 255;
    float* dst = g_out2 + ((size_t)b*512 + ch)*4096;
    const float inv = 1.f/4096.f;
    for (int i=t;i<4096;i+=256){ float2 v=S[(i>>6)*66 + (i&63)]; dst[i] = sqrtf(v.x*v.x+v.y*v.y)*inv; }
}

// ---------------- gating MLP + gate*f -> g_t ----------------
__global__ void k_gate(const float* __restrict__ w1_w, const float* __restrict__ w1_b,
                       const float* __restrict__ bnw_g, const float* __restrict__ bnw_b,
                       const float* __restrict__ bnw_m, const float* __restrict__ bnw_v,
                       const float* __restrict__ w2_w, const float* __restrict__ w2_b) {
    __shared__ float w1s[16*256];
    __shared__ float w2s[256*16];
    __shared__ float aw[16], dw[16], b2s[256];
    int b = blockIdx.x, nc = blockIdx.y;
    int t = threadIdx.x;
    for (int e=t;e<4096;e+=256){ w1s[e]=w1_w[e]; w2s[e]=w2_w[e]; }
    if (t<16){ float a = bnw_g[t]*rsqrtf(bnw_v[t]+1e-5f); aw[t]=a; dw[t]=(w1_b[t]-bnw_m[t])*a + bnw_b[t]; }
    b2s[t]=w2_b[t];
    __syncthreads();
    int n = nc*256 + t;
    const float2* fb = g_f + (size_t)b*256*4096 + n;
    float g1[16];
    #pragma unroll
    for (int j=0;j<16;j++) g1[j]=0.f;
    for (int c=0;c<256;c++){
        float v = fb[(size_t)c*4096].x;
        #pragma unroll
        for (int j=0;j<16;j++) g1[j] = fmaf(w1s[j*256+c], v, g1[j]);
    }
    #pragma unroll
    for (int j=0;j<16;j++) g1[j] = fmaxf(fmaf(g1[j], aw[j], dw[j]), 0.f);
    float2* ob = g_t + (size_t)b*256*4096 + n;
    for (int c=0;c<256;c++){
        float s = b2s[c];
        #pragma unroll
        for (int j=0;j<16;j++) s = fmaf(w2s[c*16+j], g1[j], s);
        float gt = 1.f/(1.f + expf(-s));
        float2 fv = fb[(size_t)c*4096];
        ob[(size_t)c*4096] = make_float2(fv.x*gt, fv.y*gt);
    }
}

// ---------------- ifft2 64x64 of gate*f ----------------
__global__ void k_ifft2_gate() {
    __shared__ float2 S[4096];
    int img = blockIdx.x;
    int t = threadIdx.x;
    const float2* src = g_t + (size_t)img*4096;
    for (int i=t;i<4096;i+=256) S[i]=src[i];
    __syncthreads();
    int k=t&63, rg=t>>6;
    float2 acc[16];
    #pragma unroll
    for(int i=0;i<16;i++)acc[i]=make_float2(0.f,0.f);
    for (int n=0;n<64;n++){
        float2 d = g_D64i[n*64+k];
        #pragma unroll
        for (int i=0;i<16;i++){
            float2 a = S[(rg*16+i)*64+n];
            acc[i].x = fmaf(a.x,d.x,fmaf(-a.y,d.y,acc[i].x));
            acc[i].y = fmaf(a.x,d.y,fmaf( a.y,d.x,acc[i].y));
        }
    }
    __syncthreads();
    #pragma unroll
    for (int i=0;i<16;i++) S[(rg*16+i)*64+k]=acc[i];
    __syncthreads();
    #pragma unroll
    for(int i=0;i<16;i++)acc[i]=make_float2(0.f,0.f);
    for (int r=0;r<64;r++){
        float2 bv = S[r*64+k];
        #pragma unroll
        for (int i=0;i<16;i++){
            float2 d = g_D64i[r*64+rg*16+i];
            acc[i].x = fmaf(bv.x,d.x,fmaf(-bv.y,d.y,acc[i].x));
            acc[i].y = fmaf(bv.x,d.y,fmaf( bv.y,d.x,acc[i].y));
        }
    }
    int b = img>>8, ch = img&255;
    float* dst = g_out2 + ((size_t)b*512 + 256 + ch)*4096;
    const float inv = 1.f/4096.f;
    #pragma unroll
    for (int i=0;i<16;i++){
        float2 v = acc[i];
        dst[(rg*16+i)*64 + k] = sqrtf(v.x*v.x+v.y*v.y)*inv;
    }
}

// ---------------- residual add + bf16 split transpose -> [n][ch] ----------------
__global__ void k_addx(const float* __restrict__ x) {
    __shared__ float s[32][33];
    int b = blockIdx.z;
    int ch0 = blockIdx.y*32;
    int n0 = blockIdx.x*32;
    int tj = threadIdx.x & 31;
    int ti = threadIdx.x >> 5;
    for (int i=ti;i<32;i+=8)
        s[i][tj] = g_out2[((size_t)b*512 + ch0+i)*4096 + n0 + tj];
    __syncthreads();
    for (int j=ti;j<32;j+=8) {
        int n = n0 + j, ch = ch0 + tj;
        size_t oidx = ((size_t)b*4096 + n)*512 + ch;
        float v = s[tj][j] + x[oidx];
        __nv_bfloat16 h = __float2bfloat16(v);
        g_o2hi[oidx] = h;
        g_o2lo[oidx] = __float2bfloat16(v - __bfloat162float(h));
    }
}

// ---------------- projection GEMM via HMMA ----------------
__global__ void __launch_bounds__(256, 1) k_proj_hmma(const float* __restrict__ pb,
                                                      float* __restrict__ out) {
    extern __shared__ char smem[];
    uint32_t sb = smem_u32(smem);
    int tid = threadIdx.x, wid = tid >> 5, lane = tid & 31;
    int b = blockIdx.z;
    int m0 = blockIdx.x << 7;
    int nt0 = blockIdx.y << 8;
    int wm = wid & 1, wn = wid >> 1;

    float c[4][8][4];
    #pragma unroll
    for (int i = 0; i < 4; i++)
        #pragma unroll
        for (int j = 0; j < 8; j++)
            #pragma unroll
            for (int r = 0; r < 4; r++) c[i][j][r] = 0.f;

    auto issue = [&](int chunk) {
        int pass = chunk >> 3, c0 = (chunk & 7) << 6;
        const __nv_bfloat16* as = ((pass == 2) ? g_o2lo : g_o2hi) + ((size_t)b*4096 + m0)*512 + c0;
        const __nv_bfloat16* ws = ((pass == 1) ? g_pwlo : g_pwhi) + (size_t)nt0*512 + c0;
        uint32_t bo = (uint32_t)(chunk % CONV_STAGES) * CH_BYTES;
        #pragma unroll
        for (int i = 0; i < 4; i++) {
            int idx = tid + i*256;
            int r = idx >> 3, q = idx & 7;
            cp_async16(sb + bo + swz128((uint32_t)(r*128 + q*16)), as + (size_t)r*512 + q*8, 16);
        }
        #pragma unroll
        for (int i = 0; i < 8; i++) {
            int idx = tid + i*256;
            int o = idx >> 3, q = idx & 7;
            cp_async16(sb + bo + 16384u + swz128((uint32_t)(o*128 + q*16)),
                       ws + (size_t)o*512 + q*8, 16);
        }
        asm volatile("cp.async.commit_group;" ::: "memory");
    };

    issue(0); issue(1);
    int sub = lane >> 3, lr = lane & 7;
    #pragma unroll 1
    for (int ch = 0; ch < 24; ch++) {
        if (ch + 2 < 24) {
            issue(ch + 2);
            asm volatile("cp.async.wait_group 2;" ::: "memory");
        } else {
            asm volatile("cp.async.wait_group 0;" ::: "memory");
        }
        __syncthreads();
        uint32_t aBase = sb + (uint32_t)(ch % CONV_STAGES) * CH_BYTES;
        uint32_t bBase = aBase + 16384u;
        #pragma unroll
        for (int k16 = 0; k16 < 4; k16++) {
            uint32_t kb = (uint32_t)(k16*32);
            uint32_t a[4][4];
            #pragma unroll
            for (int mf = 0; mf < 4; mf++) {
                uint32_t row = (uint32_t)(wm*64 + mf*16 + ((sub & 1) << 3) + lr);
                uint32_t col = kb + ((uint32_t)(sub >> 1) << 4);
                ldmx4(a[mf], aBase + swz128(row*128 + col));
            }
            #pragma unroll
            for (int nfp = 0; nfp < 4; nfp++) {
                uint32_t brow = (uint32_t)(wn*64 + nfp*16 + ((sub & 2) << 2) + lr);
                uint32_t bcol = kb + ((uint32_t)(sub & 1) << 4);
                uint32_t bf[4];
                ldmx4(bf, bBase + swz128(brow*128 + bcol));
                #pragma unroll
                for (int mf = 0; mf < 4; mf++) {
                    mma16816(c[mf][nfp*2],     a[mf], bf[0], bf[1]);
                    mma16816(c[mf][nfp*2 + 1], a[mf], bf[2], bf[3]);
                }
            }
        }
        __syncthreads();
    }

    #pragma unroll
    for (int nf = 0; nf < 8; nf++) {
        int o = nt0 + wn*64 + nf*8 + (lane & 3)*2;
        float p0 = pb[o], p1 = pb[o+1];
        #pragma unroll
        for (int mf = 0; mf < 4; mf++) {
            int n = m0 + wm*64 + mf*16 + (lane >> 2);
            float* d = out + ((size_t)b*4096 + n)*512 + o;
            d[0]   = c[mf][nf][0] + p0;
            d[1]   = c[mf][nf][1] + p1;
            d += 8*512;
            d[0]   = c[mf][nf][2] + p0;
            d[1]   = c[mf][nf][3] + p1;
        }
    }
}

// ---------------- launch ----------------
extern "C" void kernel_launch(void* const* d_in, const int* in_sizes, int n_in,
                              void* d_out, int out_size) {
    const float* x        = (const float*)d_in[0];
    const float* conv2_w  = (const float*)d_in[1];
    const float* conv2_b  = (const float*)d_in[2];
    const float* bn2_g    = (const float*)d_in[3];
    const float* bn2_b    = (const float*)d_in[4];
    const float* bn2_m    = (const float*)d_in[5];
    const float* bn2_v    = (const float*)d_in[6];
    const float* temp     = (const float*)d_in[7];
    const float* w1_w     = (const float*)d_in[8];
    const float* w1_b     = (const float*)d_in[9];
    const float* bnw_g    = (const float*)d_in[10];
    const float* bnw_b    = (const float*)d_in[11];
    const float* bnw_m    = (const float*)d_in[12];
    const float* bnw_v    = (const float*)d_in[13];
    const float* w2_w     = (const float*)d_in[14];
    const float* w2_b     = (const float*)d_in[15];
    const float* proj_w   = (const float*)d_in[16];
    const float* proj_b   = (const float*)d_in[17];
    float* out = (float*)d_out;

    static bool attr_set = false;
    if (!attr_set) {
        cudaFuncSetAttribute(k_conv_hmma, cudaFuncAttributeMaxDynamicSharedMemorySize, CONV_SMEM);
        cudaFuncSetAttribute(k_proj_hmma, cudaFuncAttributeMaxDynamicSharedMemorySize, CONV_SMEM);
        attr_set = true;
    }

    k_split_x<<<65536,256>>>(x);
    k_split_w<<<4608,256>>>(conv2_w);
    k_split_pw<<<1024,256>>>(proj_w);
    k_prep_misc<<<1024,256>>>(conv2_b, bn2_g, bn2_b, bn2_m, bn2_v);
    k_conv_hmma<<<256,256,CONV_SMEM>>>();
    k_fft2_fwd<<<2048,256>>>();
    k_invnorm<<<2048,256>>>();
    k_attn<<<dim3(64,4),256>>>();
    k_softmax_mkM<<<64,256>>>(temp);
    k_apply<<<dim3(64,16),256>>>();
    k_ifft4096<<<2048,256>>>();
    k_gate<<<dim3(8,16),256>>>(w1_w,w1_b,bnw_g,bnw_b,bnw_m,bnw_v,w2_w,w2_b);
    k_ifft2_gate<<<2048,256>>>();
    k_addx<<<dim3(128,16,8),256>>>(x);
    k_proj_hmma<<<dim3(32,2,8),256,CONV_SMEM>>>(proj_b, out);
}

// round 9
// speedup vs baseline: 1.5687x; 1.5687x over previous
#include <cuda_runtime.h>
#include <cuda_bf16.h>
#include <math.h>
#include <stdint.h>

#define PI_D 3.14159265358979323846

__device__ __forceinline__ uint32_t smem_u32(const void* p) {
    uint32_t a;
    asm("{ .reg .u64 t; cvta.to.shared.u64 t, %1; cvt.u32.u64 %0, t; }" : "=r"(a) : "l"(p));
    return a;
}
static __device__ __forceinline__ uint32_t swz128(uint32_t off) { return off ^ ((off >> 3) & 0x70); }

__device__ __forceinline__ void cp_async16(uint32_t saddr, const void* gaddr, int sz) {
    asm volatile("cp.async.cg.shared.global [%0], [%1], 16, %2;"
                 :: "r"(saddr), "l"(gaddr), "r"(sz) : "memory");
}
__device__ __forceinline__ void ldmx4(uint32_t* r, uint32_t addr) {
    asm volatile("ldmatrix.sync.aligned.m8n8.x4.shared.b16 {%0,%1,%2,%3}, [%4];"
        : "=r"(r[0]), "=r"(r[1]), "=r"(r[2]), "=r"(r[3]) : "r"(addr));
}
__device__ __forceinline__ void mma16816(float* c, const uint32_t* a, uint32_t b0, uint32_t b1) {
    asm volatile("mma.sync.aligned.m16n8k16.row.col.f32.bf16.bf16.f32 "
        "{%0,%1,%2,%3}, {%4,%5,%6,%7}, {%8,%9}, {%0,%1,%2,%3};"
        : "+f"(c[0]), "+f"(c[1]), "+f"(c[2]), "+f"(c[3])
        : "r"(a[0]), "r"(a[1]), "r"(a[2]), "r"(a[3]), "r"(b0), "r"(b1));
}

// ---------------- device scratch ----------------
__device__ float  g_s2[256], g_b2[256];
__device__ float  g_conv[8*256*4096];
__device__ float2 g_f[8*256*4096];
__device__ float2 g_t[8*256*4096];
__device__ float  g_out2[8*512*4096];
__device__ float2 g_attnp[4*64*1024];
__device__ float2 g_M[64*1024];          // M = D32^T * softmax(attn), per (b,hd)
__device__ float  g_invn[2048];
__device__ float2 g_D64f[4096];
__device__ float2 g_D64i[4096];
__device__ float2 g_tw[4096];
__device__ float2 g_D32i[1024];
__device__ __nv_bfloat16 g_xhi[8*4096*512];
__device__ __nv_bfloat16 g_xlo[8*4096*512];
__device__ __nv_bfloat16 g_whi[9*256*512];
__device__ __nv_bfloat16 g_wlo[9*256*512];
__device__ __nv_bfloat16 g_o2hi[8*4096*512];
__device__ __nv_bfloat16 g_o2lo[8*4096*512];
__device__ __nv_bfloat16 g_pwhi[512*512];
__device__ __nv_bfloat16 g_pwlo[512*512];

// ---------------- prep ----------------
__global__ void k_split_x(const float* __restrict__ x) {
    size_t i = (size_t)blockIdx.x * 256 + threadIdx.x;
    if (i >= (size_t)8*4096*512) return;
    float v = x[i];
    __nv_bfloat16 h = __float2bfloat16(v);
    g_xhi[i] = h;
    g_xlo[i] = __float2bfloat16(v - __bfloat162float(h));
}

__global__ void k_split_w(const float* __restrict__ w) {
    int i = blockIdx.x * 256 + threadIdx.x;
    if (i >= 9*256*512) return;
    int c = i & 511, o = (i >> 9) & 255, tap = i >> 17;
    float v = w[(o*512 + c)*9 + tap];
    __nv_bfloat16 h = __float2bfloat16(v);
    g_whi[i] = h;
    g_wlo[i] = __float2bfloat16(v - __bfloat162float(h));
}

__global__ void k_split_pw(const float* __restrict__ pw) {
    int i = blockIdx.x * 256 + threadIdx.x;
    if (i >= 512*512) return;
    float v = pw[i];
    __nv_bfloat16 h = __float2bfloat16(v);
    g_pwhi[i] = h;
    g_pwlo[i] = __float2bfloat16(v - __bfloat162float(h));
}

__global__ void k_prep_misc(const float* __restrict__ conv2_b, const float* __restrict__ g,
                            const float* __restrict__ bb, const float* __restrict__ m,
                            const float* __restrict__ v) {
    int i = blockIdx.x*blockDim.x + threadIdx.x;
    if (i < 4096) {
        int j = i >> 6, k = i & 63;
        double s, c;
        sincos(2.0*PI_D*(double)(j*k)/64.0, &s, &c);
        g_D64f[i] = make_float2((float)c, (float)(-s));
        g_D64i[i] = make_float2((float)c, (float)s);
        sincos(2.0*PI_D*(double)(j*k)/4096.0, &s, &c);
        g_tw[i] = make_float2((float)c, (float)s);
    }
    if (i < 1024) {
        int j = i >> 5, k = i & 31;
        double s, c;
        sincos(2.0*PI_D*(double)(j*k)/32.0, &s, &c);
        g_D32i[i] = make_float2((float)(c/32.0), (float)(s/32.0));
    }
    if (i < 256) {
        float sc = g[i] * rsqrtf(v[i] + 1e-5f);
        g_s2[i] = sc;
        g_b2[i] = (conv2_b[i] - m[i]) * sc + bb[i];
    }
    if (i < 4*64*1024) g_attnp[i] = make_float2(0.f, 0.f);
}

// ---------------- conv via HMMA implicit GEMM ----------------
#define CH_BYTES 49152
#define CONV_STAGES 3
#define CONV_SMEM (CONV_STAGES*CH_BYTES)

__global__ void __launch_bounds__(256, 1) k_conv_hmma() {
    extern __shared__ char smem[];
    uint32_t sb = smem_u32(smem);
    int tid = threadIdx.x, wid = tid >> 5, lane = tid & 31;
    int b = blockIdx.x >> 5;
    int m0 = (blockIdx.x & 31) << 7;
    int wm = wid & 1, wn = wid >> 1;

    float c[4][8][4];
    #pragma unroll
    for (int i = 0; i < 4; i++)
        #pragma unroll
        for (int j = 0; j < 8; j++)
            #pragma unroll
            for (int r = 0; r < 4; r++) c[i][j][r] = 0.f;

    auto issue = [&](int chunk) {
        int pass = chunk / 72, rem = chunk % 72, tap = rem >> 3, c0 = (rem & 7) << 6;
        const __nv_bfloat16* xs = ((pass == 2) ? g_xlo : g_xhi) + (size_t)b*4096*512 + c0;
        const __nv_bfloat16* ws = ((pass == 1) ? g_wlo : g_whi) + (size_t)tap*256*512 + c0;
        int oy = (tap/3)*3 - 3, ox = (tap%3)*3 - 3;
        uint32_t bo = (uint32_t)(chunk % CONV_STAGES) * CH_BYTES;
        #pragma unroll
        for (int i = 0; i < 4; i++) {
            int idx = tid + i*256;
            int r = idx >> 3, q = idx & 7;
            int n = m0 + r;
            int ysr = (n >> 6) + oy, xsr = (n & 63) + ox;
            bool ok = ((unsigned)ysr < 64u) && ((unsigned)xsr < 64u);
            const __nv_bfloat16* gp = ok ? (xs + (size_t)(ysr*64 + xsr)*512 + q*8) : xs;
            cp_async16(sb + bo + swz128((uint32_t)(r*128 + q*16)), gp, ok ? 16 : 0);
        }
        #pragma unroll
        for (int i = 0; i < 8; i++) {
            int idx = tid + i*256;
            int o = idx >> 3, q = idx & 7;
            cp_async16(sb + bo + 16384u + swz128((uint32_t)(o*128 + q*16)),
                       ws + (size_t)o*512 + q*8, 16);
        }
        asm volatile("cp.async.commit_group;" ::: "memory");
    };

    issue(0); issue(1);
    int sub = lane >> 3, lr = lane & 7;
    #pragma unroll 1
    for (int ch = 0; ch < 216; ch++) {
        if (ch + 2 < 216) {
            issue(ch + 2);
            asm volatile("cp.async.wait_group 2;" ::: "memory");
        } else {
            asm volatile("cp.async.wait_group 0;" ::: "memory");
        }
        __syncthreads();
        uint32_t aBase = sb + (uint32_t)(ch % CONV_STAGES) * CH_BYTES;
        uint32_t bBase = aBase + 16384u;
        #pragma unroll
        for (int k16 = 0; k16 < 4; k16++) {
            uint32_t kb = (uint32_t)(k16*32);
            uint32_t a[4][4];
            #pragma unroll
            for (int mf = 0; mf < 4; mf++) {
                uint32_t row = (uint32_t)(wm*64 + mf*16 + ((sub & 1) << 3) + lr);
                uint32_t col = kb + ((uint32_t)(sub >> 1) << 4);
                ldmx4(a[mf], aBase + swz128(row*128 + col));
            }
            #pragma unroll
            for (int nfp = 0; nfp < 4; nfp++) {
                uint32_t brow = (uint32_t)(wn*64 + nfp*16 + ((sub & 2) << 2) + lr);
                uint32_t bcol = kb + ((uint32_t)(sub & 1) << 4);
                uint32_t bf[4];
                ldmx4(bf, bBase + swz128(brow*128 + bcol));
                #pragma unroll
                for (int mf = 0; mf < 4; mf++) {
                    mma16816(c[mf][nfp*2],     a[mf], bf[0], bf[1]);
                    mma16816(c[mf][nfp*2 + 1], a[mf], bf[2], bf[3]);
                }
            }
        }
        __syncthreads();
    }

    #pragma unroll
    for (int nf = 0; nf < 8; nf++) {
        int o = wn*64 + nf*8 + (lane & 3)*2;
        float s0 = g_s2[o],   t0 = g_b2[o];
        float s1 = g_s2[o+1], t1 = g_b2[o+1];
        float* d0 = g_conv + ((size_t)b*256 + o)*4096;
        float* d1 = d0 + 4096;
        #pragma unroll
        for (int mf = 0; mf < 4; mf++) {
            int n = m0 + wm*64 + mf*16 + (lane >> 2);
            d0[n]   = fmaxf(fmaf(c[mf][nf][0], s0, t0), 0.f);
            d1[n]   = fmaxf(fmaf(c[mf][nf][1], s1, t1), 0.f);
            d0[n+8] = fmaxf(fmaf(c[mf][nf][2], s0, t0), 0.f);
            d1[n+8] = fmaxf(fmaf(c[mf][nf][3], s1, t1), 0.f);
        }
    }
}

// ---------------- fft2 64x64 forward (REAL input) + fused norm ----------------
__global__ void k_fft2_fwd() {
    __shared__ float2 S[4096];
    __shared__ float red[256];
    float* Sr = (float*)S;
    int img = blockIdx.x;
    int t = threadIdx.x;
    const float* src = g_conv + (size_t)img*4096;
    for (int i=t;i<4096;i+=256) Sr[i] = src[i];
    __syncthreads();
    int k = t & 63, rg = t >> 6;
    float2 acc[16];
    #pragma unroll
    for (int i=0;i<16;i++) acc[i]=make_float2(0.f,0.f);
    for (int n=0;n<64;n++) {
        float2 d = g_D64f[n*64+k];
        #pragma unroll
        for (int i=0;i<16;i++) {
            float a = Sr[(rg*16+i)*64 + n];
            acc[i].x = fmaf(a, d.x, acc[i].x);
            acc[i].y = fmaf(a, d.y, acc[i].y);
        }
    }
    __syncthreads();
    #pragma unroll
    for (int i=0;i<16;i++) S[(rg*16+i)*64 + k] = acc[i];
    __syncthreads();
    #pragma unroll
    for (int i=0;i<16;i++) acc[i]=make_float2(0.f,0.f);
    for (int r=0;r<64;r++) {
        float2 bv = S[r*64 + k];
        #pragma unroll
        for (int i=0;i<16;i++) {
            float2 d = g_D64f[r*64 + rg*16 + i];
            acc[i].x = fmaf(bv.x, d.x, fmaf(-bv.y, d.y, acc[i].x));
            acc[i].y = fmaf(bv.x, d.y, fmaf( bv.y, d.x, acc[i].y));
        }
    }
    float2* dst = g_f + (size_t)img*4096;
    float nrm = 0.f;
    #pragma unroll
    for (int i=0;i<16;i++) {
        dst[(rg*16+i)*64 + k] = acc[i];
        nrm = fmaf(acc[i].x, acc[i].x, fmaf(acc[i].y, acc[i].y, nrm));
    }
    red[t] = nrm; __syncthreads();
    for (int st=128;st>0;st>>=1){ if(t<st) red[t]+=red[t+st]; __syncthreads(); }
    if (t==0) g_invn[img] = 1.f / fmaxf(sqrtf(red[0]), 1e-12f);
}

// ---------------- attention logit partials ----------------
__global__ void k_attn() {
    __shared__ float2 F[32*65];
    int bh = blockIdx.x, p = blockIdx.y;
    int b = bh >> 3, hd = bh & 7;
    int t = threadIdx.x;
    int d = t & 31, cg = t >> 5;
    float2 acc[4];
    #pragma unroll
    for (int i=0;i<4;i++) acc[i]=make_float2(0.f,0.f);
    const float2* base = g_f + (((size_t)b*256 + hd*32)*4096);
    for (int n0 = p*1024; n0 < p*1024+1024; n0 += 64) {
        __syncthreads();
        for (int e=t; e<2048; e+=256) {
            int cc = e >> 6, j = e & 63;
            F[cc*65+j] = base[(size_t)cc*4096 + n0 + j];
        }
        __syncthreads();
        for (int j=0;j<64;j++) {
            float2 vd = F[d*65+j];
            #pragma unroll
            for (int i=0;i<4;i++) {
                float2 vc = F[(cg*4+i)*65 + j];
                acc[i].x = fmaf(vc.x,vd.x, fmaf(-vc.y,vd.y, acc[i].x));
                acc[i].y = fmaf(vc.x,vd.y, fmaf( vc.y,vd.x, acc[i].y));
            }
        }
    }
    float2* dst = g_attnp + ((size_t)p*64 + bh)*1024;
    #pragma unroll
    for (int i=0;i<4;i++) dst[(cg*4+i)*32 + d] = acc[i];
}

// ---------------- softmax + M = D32^T * attn (fused) ----------------
__global__ void k_softmax_mkM(const float* __restrict__ temperature) {
    __shared__ float2 A[1024];
    int bh = blockIdx.x;
    int b = bh >> 3, hd = bh & 7;
    int t = threadIdx.x;
    int w = t >> 5, lane = t & 31;
    float temp = temperature[hd];
    #pragma unroll
    for (int rr = 0; rr < 4; rr++) {
        int c = w*4 + rr;
        size_t idx = (size_t)bh*1024 + c*32 + lane;
        float2 v = make_float2(0.f,0.f);
        #pragma unroll
        for (int p=0;p<4;p++){ float2 q = g_attnp[(size_t)p*65536 + idx]; v.x+=q.x; v.y+=q.y; }
        float scale = g_invn[b*256 + hd*32 + c] * g_invn[b*256 + hd*32 + lane] * temp;
        float re = v.x*scale, im = v.y*scale;
        float mre = re, mim = im;
        for (int s=16;s>0;s>>=1){ mre = fmaxf(mre, __shfl_xor_sync(0xffffffffu, mre, s));
                                  mim = fmaxf(mim, __shfl_xor_sync(0xffffffffu, mim, s)); }
        float ere = expf(re-mre), eim = expf(im-mim);
        float sre=ere, sim=eim;
        for (int s=16;s>0;s>>=1){ sre += __shfl_xor_sync(0xffffffffu,sre,s);
                                  sim += __shfl_xor_sync(0xffffffffu,sim,s); }
        A[c*32 + lane] = make_float2(ere/sre, eim/sim);
    }
    __syncthreads();
    int d = t & 31, kg = t >> 5;
    #pragma unroll
    for (int kk = 0; kk < 4; kk++) {
        int k = kg*4 + kk;
        float2 acc = make_float2(0.f, 0.f);
        for (int c = 0; c < 32; c++) {
            float2 Dv = g_D32i[c*32 + k];
            float2 av = A[c*32 + d];
            acc.x = fmaf(Dv.x, av.x, fmaf(-Dv.y, av.y, acc.x));
            acc.y = fmaf(Dv.x, av.y, fmaf( Dv.y, av.x, acc.y));
        }
        g_M[(size_t)bh*1024 + k*32 + d] = acc;
    }
}

// ---------------- apply (M = ifft32-folded attention) ----------------
__global__ void k_apply() {
    __shared__ float2 As[1024];
    int bh = blockIdx.x, nc = blockIdx.y;
    int b = bh>>3, hd = bh&7;
    int t = threadIdx.x;
    for (int e=t;e<1024;e+=256) As[e] = g_M[(size_t)bh*1024 + e];
    __syncthreads();
    int n = nc*256 + t;
    const float2* fb = g_f + ((size_t)b*256 + hd*32)*4096 + n;
    float2 acc[32];
    #pragma unroll
    for (int c=0;c<32;c++) acc[c]=make_float2(0.f,0.f);
    for (int d=0;d<32;d++) {
        float2 v = fb[(size_t)d*4096];
        #pragma unroll
        for (int c=0;c<32;c++) {
            float2 a = As[c*32+d];
            acc[c].x = fmaf(a.x,v.x, fmaf(-a.y,v.y, acc[c].x));
            acc[c].y = fmaf(a.x,v.y, fmaf( a.y,v.x, acc[c].y));
        }
    }
    float2* ob = g_t + ((size_t)b*256 + hd*32)*4096 + n;
    #pragma unroll
    for (int c=0;c<32;c++) ob[(size_t)c*4096] = acc[c];
}

// ---------------- ifft-4096 per row ----------------
__global__ void k_ifft4096() {
    __shared__ float2 S[4224];
    int row = blockIdx.x;
    int t = threadIdx.x;
    const float2* src = g_t + (size_t)row*4096;
    for (int i=t;i<4096;i+=256) S[i]=src[i];
    __syncthreads();
    int k = t&63, rg = t>>6;
    float2 acc[16];
    #pragma unroll
    for(int i=0;i<16;i++)acc[i]=make_float2(0.f,0.f);
    for (int n1=0;n1<64;n1++){
        float2 a = S[n1*64 + k];
        #pragma unroll
        for (int i=0;i<16;i++){
            float2 d = g_D64i[n1*64 + rg*16+i];
            acc[i].x = fmaf(a.x,d.x,fmaf(-a.y,d.y,acc[i].x));
            acc[i].y = fmaf(a.x,d.y,fmaf( a.y,d.x,acc[i].y));
        }
    }
    __syncthreads();
    #pragma unroll
    for (int i=0;i<16;i++){
        int k1 = rg*16+i;
        float2 tw = g_tw[k*64 + k1];
        float2 v; v.x = acc[i].x*tw.x - acc[i].y*tw.y; v.y = acc[i].x*tw.y + acc[i].y*tw.x;
        S[k1*64 + k] = v;
    }
    __syncthreads();
    #pragma unroll
    for(int i=0;i<16;i++)acc[i]=make_float2(0.f,0.f);
    for (int n2=0;n2<64;n2++){
        float2 d = g_D64i[n2*64 + k];
        #pragma unroll
        for (int i=0;i<16;i++){
            float2 bv = S[(rg*16+i)*64 + n2];
            acc[i].x = fmaf(bv.x,d.x,fmaf(-bv.y,d.y,acc[i].x));
            acc[i].y = fmaf(bv.x,d.y,fmaf( bv.y,d.x,acc[i].y));
        }
    }
    __syncthreads();
    #pragma unroll
    for (int i=0;i<16;i++) S[k*66 + rg*16+i] = acc[i];
    __syncthreads();
    int b = row >> 8, ch = row & 255;
    float* dst = g_out2 + ((size_t)b*512 + ch)*4096;
    const float inv = 1.f/4096.f;
    for (int i=t;i<4096;i+=256){ float2 v=S[(i>>6)*66 + (i&63)]; dst[i] = sqrtf(v.x*v.x+v.y*v.y)*inv; }
}

// ---------------- gating MLP + gate*f -> g_t ----------------
__global__ void k_gate(const float* __restrict__ w1_w, const float* __restrict__ w1_b,
                       const float* __restrict__ bnw_g, const float* __restrict__ bnw_b,
                       const float* __restrict__ bnw_m, const float* __restrict__ bnw_v,
                       const float* __restrict__ w2_w, const float* __restrict__ w2_b) {
    __shared__ float w1s[16*256];
    __shared__ float w2s[256*16];
    __shared__ float aw[16], dw[16], b2s[256];
    int b = blockIdx.x, nc = blockIdx.y;
    int t = threadIdx.x;
    for (int e=t;e<4096;e+=256){ w1s[e]=w1_w[e]; w2s[e]=w2_w[e]; }
    if (t<16){ float a = bnw_g[t]*rsqrtf(bnw_v[t]+1e-5f); aw[t]=a; dw[t]=(w1_b[t]-bnw_m[t])*a + bnw_b[t]; }
    b2s[t]=w2_b[t];
    __syncthreads();
    int n = nc*256 + t;
    const float2* fb = g_f + (size_t)b*256*4096 + n;
    float g1[16];
    #pragma unroll
    for (int j=0;j<16;j++) g1[j]=0.f;
    for (int c=0;c<256;c++){
        float v = fb[(size_t)c*4096].x;
        #pragma unroll
        for (int j=0;j<16;j++) g1[j] = fmaf(w1s[j*256+c], v, g1[j]);
    }
    #pragma unroll
    for (int j=0;j<16;j++) g1[j] = fmaxf(fmaf(g1[j], aw[j], dw[j]), 0.f);
    float2* ob = g_t + (size_t)b*256*4096 + n;
    for (int c=0;c<256;c++){
        float s = b2s[c];
        #pragma unroll
        for (int j=0;j<16;j++) s = fmaf(w2s[c*16+j], g1[j], s);
        float gt = 1.f/(1.f + expf(-s));
        float2 fv = fb[(size_t)c*4096];
        ob[(size_t)c*4096] = make_float2(fv.x*gt, fv.y*gt);
    }
}

// ---------------- ifft2 64x64 of gate*f  (radix-8x8) ----------------
__global__ void k_ifft2_gate() {
    __shared__ float2 S[64*65];     // padded row stride 65
    __shared__ float2 W8[64];       // exp(+2pi i a c / 8), idx a*8+c
    __shared__ float2 TW[64];       // exp(+2pi i b c / 64), idx b*8+c
    int img = blockIdx.x;
    int t = threadIdx.x;
    if (t < 64) {
        int a = t >> 3, c = t & 7;
        W8[t] = g_D64i[64 + ((a*c*8) & 63)];
        TW[t] = g_D64i[64 + a*c];
    }
    const float2* src = g_t + (size_t)img*4096;
    for (int i=t;i<4096;i+=256) S[(i>>6)*65 + (i&63)] = src[i];
    __syncthreads();

    int q = t & 3;
    // ===== pass 1: transform each ROW (64 rows, 4 threads/row) =====
    {
        int row = t >> 2;
        float2* Sr = S + row*65;
        float2 Tt[2][8];
        #pragma unroll
        for (int bb=0; bb<2; bb++) {
            int b = q*2 + bb;
            float2 in[8];
            #pragma unroll
            for (int a=0;a<8;a++) in[a] = Sr[8*a + b];
            #pragma unroll
            for (int c=0;c<8;c++) {
                float2 acc = make_float2(0.f,0.f);
                #pragma unroll
                for (int a=0;a<8;a++) {
                    float2 w = W8[a*8+c];
                    acc.x = fmaf(in[a].x,w.x, fmaf(-in[a].y,w.y, acc.x));
                    acc.y = fmaf(in[a].x,w.y, fmaf( in[a].y,w.x, acc.y));
                }
                float2 tw = TW[b*8+c];
                Tt[bb][c].x = acc.x*tw.x - acc.y*tw.y;
                Tt[bb][c].y = acc.x*tw.y + acc.y*tw.x;
            }
        }
        __syncthreads();
        #pragma unroll
        for (int bb=0;bb<2;bb++){ int b=q*2+bb;
            #pragma unroll
            for (int c=0;c<8;c++) Sr[b*8+c] = Tt[bb][c];
        }
        __syncthreads();
        float2 Ot[2][8];
        #pragma unroll
        for (int cc=0;cc<2;cc++){ int c=q*2+cc;
            float2 in[8];
            #pragma unroll
            for (int b=0;b<8;b++) in[b] = Sr[b*8+c];
            #pragma unroll
            for (int d=0;d<8;d++){
                float2 acc = make_float2(0.f,0.f);
                #pragma unroll
                for (int b=0;b<8;b++){
                    float2 w = W8[b*8+d];
                    acc.x = fmaf(in[b].x,w.x, fmaf(-in[b].y,w.y,acc.x));
                    acc.y = fmaf(in[b].x,w.y, fmaf( in[b].y,w.x,acc.y));
                }
                Ot[cc][d]=acc;
            }
        }
        __syncthreads();
        #pragma unroll
        for (int cc=0;cc<2;cc++){ int c=q*2+cc;
            #pragma unroll
            for (int d=0;d<8;d++) Sr[c + 8*d] = Ot[cc][d];
        }
        __syncthreads();
    }
    // ===== pass 2: transform each COLUMN (64 cols, 4 threads/col) =====
    {
        int col = t >> 2;
        float2 Tt[2][8];
        #pragma unroll
        for (int bb=0; bb<2; bb++) {
            int b = q*2 + bb;
            float2 in[8];
            #pragma unroll
            for (int a=0;a<8;a++) in[a] = S[(8*a + b)*65 + col];
            #pragma unroll
            for (int c=0;c<8;c++) {
                float2 acc = make_float2(0.f,0.f);
                #pragma unroll
                for (int a=0;a<8;a++) {
                    float2 w = W8[a*8+c];
                    acc.x = fmaf(in[a].x,w.x, fmaf(-in[a].y,w.y, acc.x));
                    acc.y = fmaf(in[a].x,w.y, fmaf( in[a].y,w.x, acc.y));
                }
                float2 tw = TW[b*8+c];
                Tt[bb][c].x = acc.x*tw.x - acc.y*tw.y;
                Tt[bb][c].y = acc.x*tw.y + acc.y*tw.x;
            }
        }
        __syncthreads();
        #pragma unroll
        for (int bb=0;bb<2;bb++){ int b=q*2+bb;
            #pragma unroll
            for (int c=0;c<8;c++) S[(b*8+c)*65 + col] = Tt[bb][c];
        }
        __syncthreads();
        float2 Ot[2][8];
        #pragma unroll
        for (int cc=0;cc<2;cc++){ int c=q*2+cc;
            float2 in[8];
            #pragma unroll
            for (int b=0;b<8;b++) in[b] = S[(b*8+c)*65 + col];
            #pragma unroll
            for (int d=0;d<8;d++){
                float2 acc = make_float2(0.f,0.f);
                #pragma unroll
                for (int b=0;b<8;b++){
                    float2 w = W8[b*8+d];
                    acc.x = fmaf(in[b].x,w.x, fmaf(-in[b].y,w.y,acc.x));
                    acc.y = fmaf(in[b].x,w.y, fmaf( in[b].y,w.x,acc.y));
                }
                Ot[cc][d]=acc;
            }
        }
        __syncthreads();
        #pragma unroll
        for (int cc=0;cc<2;cc++){ int c=q*2+cc;
            #pragma unroll
            for (int d=0;d<8;d++) S[(c + 8*d)*65 + col] = Ot[cc][d];
        }
        __syncthreads();
    }
    int b_ = img >> 8, ch = img & 255;
    float* dst = g_out2 + ((size_t)b_*512 + 256 + ch)*4096;
    const float inv = 1.f/4096.f;
    for (int i=t;i<4096;i+=256){
        float2 v = S[(i>>6)*65 + (i&63)];
        dst[i] = sqrtf(v.x*v.x + v.y*v.y)*inv;
    }
}

// ---------------- residual add + bf16 split transpose -> [n][ch] ----------------
__global__ void k_addx(const float* __restrict__ x) {
    __shared__ float s[32][33];
    int b = blockIdx.z;
    int ch0 = blockIdx.y*32;
    int n0 = blockIdx.x*32;
    int tj = threadIdx.x & 31;
    int ti = threadIdx.x >> 5;
    for (int i=ti;i<32;i+=8)
        s[i][tj] = g_out2[((size_t)b*512 + ch0+i)*4096 + n0 + tj];
    __syncthreads();
    for (int j=ti;j<32;j+=8) {
        int n = n0 + j, ch = ch0 + tj;
        size_t oidx = ((size_t)b*4096 + n)*512 + ch;
        float v = s[tj][j] + x[oidx];
        __nv_bfloat16 h = __float2bfloat16(v);
        g_o2hi[oidx] = h;
        g_o2lo[oidx] = __float2bfloat16(v - __bfloat162float(h));
    }
}

// ---------------- projection GEMM via HMMA ----------------
__global__ void __launch_bounds__(256, 1) k_proj_hmma(const float* __restrict__ pb,
                                                      float* __restrict__ out) {
    extern __shared__ char smem[];
    uint32_t sb = smem_u32(smem);
    int tid = threadIdx.x, wid = tid >> 5, lane = tid & 31;
    int b = blockIdx.z;
    int m0 = blockIdx.x << 7;
    int nt0 = blockIdx.y << 8;
    int wm = wid & 1, wn = wid >> 1;

    float c[4][8][4];
    #pragma unroll
    for (int i = 0; i < 4; i++)
        #pragma unroll
        for (int j = 0; j < 8; j++)
            #pragma unroll
            for (int r = 0; r < 4; r++) c[i][j][r] = 0.f;

    auto issue = [&](int chunk) {
        int pass = chunk >> 3, c0 = (chunk & 7) << 6;
        const __nv_bfloat16* as = ((pass == 2) ? g_o2lo : g_o2hi) + ((size_t)b*4096 + m0)*512 + c0;
        const __nv_bfloat16* ws = ((pass == 1) ? g_pwlo : g_pwhi) + (size_t)nt0*512 + c0;
        uint32_t bo = (uint32_t)(chunk % CONV_STAGES) * CH_BYTES;
        #pragma unroll
        for (int i = 0; i < 4; i++) {
            int idx = tid + i*256;
            int r = idx >> 3, q = idx & 7;
            cp_async16(sb + bo + swz128((uint32_t)(r*128 + q*16)), as + (size_t)r*512 + q*8, 16);
        }
        #pragma unroll
        for (int i = 0; i < 8; i++) {
            int idx = tid + i*256;
            int o = idx >> 3, q = idx & 7;
            cp_async16(sb + bo + 16384u + swz128((uint32_t)(o*128 + q*16)),
                       ws + (size_t)o*512 + q*8, 16);
        }
        asm volatile("cp.async.commit_group;" ::: "memory");
    };

    issue(0); issue(1);
    int sub = lane >> 3, lr = lane & 7;
    #pragma unroll 1
    for (int ch = 0; ch < 24; ch++) {
        if (ch + 2 < 24) {
            issue(ch + 2);
            asm volatile("cp.async.wait_group 2;" ::: "memory");
        } else {
            asm volatile("cp.async.wait_group 0;" ::: "memory");
        }
        __syncthreads();
        uint32_t aBase = sb + (uint32_t)(ch % CONV_STAGES) * CH_BYTES;
        uint32_t bBase = aBase + 16384u;
        #pragma unroll
        for (int k16 = 0; k16 < 4; k16++) {
            uint32_t kb = (uint32_t)(k16*32);
            uint32_t a[4][4];
            #pragma unroll
            for (int mf = 0; mf < 4; mf++) {
                uint32_t row = (uint32_t)(wm*64 + mf*16 + ((sub & 1) << 3) + lr);
                uint32_t col = kb + ((uint32_t)(sub >> 1) << 4);
                ldmx4(a[mf], aBase + swz128(row*128 + col));
            }
            #pragma unroll
            for (int nfp = 0; nfp < 4; nfp++) {
                uint32_t brow = (uint32_t)(wn*64 + nfp*16 + ((sub & 2) << 2) + lr);
                uint32_t bcol = kb + ((uint32_t)(sub & 1) << 4);
                uint32_t bf[4];
                ldmx4(bf, bBase + swz128(brow*128 + bcol));
                #pragma unroll
                for (int mf = 0; mf < 4; mf++) {
                    mma16816(c[mf][nfp*2],     a[mf], bf[0], bf[1]);
                    mma16816(c[mf][nfp*2 + 1], a[mf], bf[2], bf[3]);
                }
            }
        }
        __syncthreads();
    }

    #pragma unroll
    for (int nf = 0; nf < 8; nf++) {
        int o = nt0 + wn*64 + nf*8 + (lane & 3)*2;
        float p0 = pb[o], p1 = pb[o+1];
        #pragma unroll
        for (int mf = 0; mf < 4; mf++) {
            int n = m0 + wm*64 + mf*16 + (lane >> 2);
            float* d = out + ((size_t)b*4096 + n)*512 + o;
            d[0]   = c[mf][nf][0] + p0;
            d[1]   = c[mf][nf][1] + p1;
            d += 8*512;
            d[0]   = c[mf][nf][2] + p0;
            d[1]   = c[mf][nf][3] + p1;
        }
    }
}

// ---------------- launch ----------------
extern "C" void kernel_launch(void* const* d_in, const int* in_sizes, int n_in,
                              void* d_out, int out_size) {
    const float* x        = (const float*)d_in[0];
    const float* conv2_w  = (const float*)d_in[1];
    const float* conv2_b  = (const float*)d_in[2];
    const float* bn2_g    = (const float*)d_in[3];
    const float* bn2_b    = (const float*)d_in[4];
    const float* bn2_m    = (const float*)d_in[5];
    const float* bn2_v    = (const float*)d_in[6];
    const float* temp     = (const float*)d_in[7];
    const float* w1_w     = (const float*)d_in[8];
    const float* w1_b     = (const float*)d_in[9];
    const float* bnw_g    = (const float*)d_in[10];
    const float* bnw_b    = (const float*)d_in[11];
    const float* bnw_m    = (const float*)d_in[12];
    const float* bnw_v    = (const float*)d_in[13];
    const float* w2_w     = (const float*)d_in[14];
    const float* w2_b     = (const float*)d_in[15];
    const float* proj_w   = (const float*)d_in[16];
    const float* proj_b   = (const float*)d_in[17];
    float* out = (float*)d_out;

    static bool attr_set = false;
    if (!attr_set) {
        cudaFuncSetAttribute(k_conv_hmma, cudaFuncAttributeMaxDynamicSharedMemorySize, CONV_SMEM);
        cudaFuncSetAttribute(k_proj_hmma, cudaFuncAttributeMaxDynamicSharedMemorySize, CONV_SMEM);
        attr_set = true;
    }

    k_split_x<<<65536,256>>>(x);
    k_split_w<<<4608,256>>>(conv2_w);
    k_split_pw<<<1024,256>>>(proj_w);
    k_prep_misc<<<1024,256>>>(conv2_b, bn2_g, bn2_b, bn2_m, bn2_v);
    k_conv_hmma<<<256,256,CONV_SMEM>>>();
    k_fft2_fwd<<<2048,256>>>();
    k_attn<<<dim3(64,4),256>>>();
    k_softmax_mkM<<<64,256>>>(temp);
    k_apply<<<dim3(64,16),256>>>();
    k_ifft4096<<<2048,256>>>();
    k_gate<<<dim3(8,16),256>>>(w1_w,w1_b,bnw_g,bnw_b,bnw_m,bnw_v,w2_w,w2_b);
    k_ifft2_gate<<<2048,256>>>();
    k_addx<<<dim3(128,16,8),256>>>(x);
    k_proj_hmma<<<dim3(32,2,8),256,CONV_SMEM>>>(proj_b, out);
}